// round 10
// baseline (speedup 1.0000x reference)
#include <cuda_runtime.h>

#define N_NODES 100000
#define N_EDGES 1200000
#define D_FEAT  64
#define D_OUT   128
#define SCAN_CHUNK  1024
#define SCAN_BLOCKS ((N_NODES + SCAN_CHUNK - 1) / SCAN_CHUNK)   // 98
#define PREP_BLOCKS 296   // 2 blocks/SM on 148 SMs -> guaranteed co-resident
#define PREP_THREADS 256

// Scratch (no allocs allowed)
__device__ int g_esrc[N_EDGES];                 // src ids binned by dst
__device__ int g_rank[N_EDGES];                 // per-edge rank within its dst bin
__device__ int g_count[N_NODES];
__device__ int g_off[N_NODES + 1];
__device__ int g_bsum[SCAN_BLOCKS];
__device__ int g_bscan[SCAN_BLOCKS];
__device__ unsigned g_bar[8];                   // ticket barriers, NEVER reset:
                                                // cohort math is replay-safe.

// Replay-safe grid barrier: each use adds exactly PREP_BLOCKS to counter id.
// A block's release target is the end of its own cohort, derived from its
// ticket — monotonic across graph replays, no reset, no deadlock (all
// PREP_BLOCKS are co-resident by construction).
__device__ __forceinline__ void gbar(int id) {
    __syncthreads();
    if (threadIdx.x == 0) {
        __threadfence();
        unsigned t = atomicAdd(&g_bar[id], 1u);
        unsigned target = t - (t % PREP_BLOCKS) + PREP_BLOCKS;
        while (atomicAdd(&g_bar[id], 0u) < target) __nanosleep(64);
    }
    __syncthreads();
}

// ---------------------------------------------------------------------------
// K-PREP (persistent, 296 blocks): zero counts -> count+rank -> 2-level scan
// -> atomic-free bin.  Replaces 4 kernel launches with barriers (~1us each).
// ---------------------------------------------------------------------------
__global__ void __launch_bounds__(PREP_THREADS) prep_kernel(
    const int* __restrict__ src, const int* __restrict__ dst)
{
    __shared__ int sh[256];
    __shared__ int sp[128];
    int bid = blockIdx.x, tid = threadIdx.x;
    int gtid = bid * PREP_THREADS + tid;
    const int gstride = PREP_BLOCKS * PREP_THREADS;

    // P0: zero per-node counters
    for (int i = gtid; i < N_NODES; i += gstride) g_count[i] = 0;
    gbar(0);

    // P1: count edges per dst; atomic return value = edge's rank in its bin
    for (int e = gtid; e < N_EDGES; e += gstride) {
        int d = __ldg(dst + e);
        int r = ((unsigned)d < N_NODES) ? atomicAdd(&g_count[d], 1) : 0;
        g_rank[e] = r;
    }
    gbar(1);

    // P2a: per-chunk sums (first SCAN_BLOCKS blocks own 1024 nodes each)
    int c[4]; int s = 0;
    int base = bid * SCAN_CHUNK + tid * 4;
    if (bid < SCAN_BLOCKS) {
        #pragma unroll
        for (int j = 0; j < 4; j++) {
            int i = base + j;
            c[j] = (i < N_NODES) ? g_count[i] : 0;
            s += c[j];
        }
        sh[tid] = s; __syncthreads();
        for (int o = 128; o; o >>= 1) { if (tid < o) sh[tid] += sh[tid + o]; __syncthreads(); }
        if (tid == 0) g_bsum[bid] = sh[0];
    }
    gbar(2);

    // P2b: block 0 scans the 98 chunk sums
    if (bid == 0) {
        int v = (tid < SCAN_BLOCKS) ? g_bsum[tid] : 0;
        if (tid < 128) sp[tid] = v;
        __syncthreads();
        #pragma unroll
        for (int o = 1; o < 128; o <<= 1) {
            int t = (tid < 128 && tid >= o) ? sp[tid - o] : 0;
            __syncthreads();
            if (tid < 128) sp[tid] += t;
            __syncthreads();
        }
        if (tid < SCAN_BLOCKS) g_bscan[tid] = sp[tid] - v;   // exclusive
        if (tid == 127) g_off[N_NODES] = sp[127];            // total
    }
    gbar(3);

    // P2c: block-local exclusive scan, write offsets
    if (bid < SCAN_BLOCKS) {
        sh[tid] = s; __syncthreads();
        int v2 = s;
        #pragma unroll
        for (int o = 1; o < 256; o <<= 1) {
            int t = (tid >= o) ? sh[tid - o] : 0;
            __syncthreads();
            sh[tid] += t;
            __syncthreads();
        }
        int run = g_bscan[bid] + (sh[tid] - v2);
        #pragma unroll
        for (int j = 0; j < 4; j++) {
            int i = base + j;
            if (i < N_NODES) { g_off[i] = run; run += c[j]; }
        }
    }
    gbar(4);

    // P3: atomic-free bin: slot = off[dst] + rank
    for (int e = gtid; e < N_EDGES; e += gstride) {
        int d = __ldg(dst + e);
        if ((unsigned)d >= N_NODES) continue;
        g_esrc[__ldg(&g_off[d]) + __ldg(&g_rank[e])] = __ldg(src + e);
    }
}

// ---------------------------------------------------------------------------
// K-MAIN: FUSED attention + FC, half-warp + pipelined loads.
// __launch_bounds__(256, 4): force <=62 regs -> 4 blocks/SM (32 warps).
// R9 analysis: issue/shuffle/MUFU throughput all have headroom; at ~80 regs
// the regfile capped residency at 3 blocks (24 warps) — occupancy was the
// hidden latency-hiding limit.
// ---------------------------------------------------------------------------
__device__ __forceinline__ void accum4(float4& acc, const float4 r,
                                       const float4 w0, const float4 w1,
                                       const float4 w2, const float4 w3) {
    acc.x = fmaf(r.x, w0.x, fmaf(r.y, w1.x, fmaf(r.z, w2.x, fmaf(r.w, w3.x, acc.x))));
    acc.y = fmaf(r.x, w0.y, fmaf(r.y, w1.y, fmaf(r.z, w2.y, fmaf(r.w, w3.y, acc.y))));
    acc.z = fmaf(r.x, w0.z, fmaf(r.y, w1.z, fmaf(r.z, w2.z, fmaf(r.w, w3.z, acc.z))));
    acc.w = fmaf(r.x, w0.w, fmaf(r.y, w1.w, fmaf(r.z, w2.w, fmaf(r.w, w3.w, acc.w))));
}

__device__ __forceinline__ float4 relu4(float4 v) {
    v.x = fmaxf(v.x, 0.f); v.y = fmaxf(v.y, 0.f);
    v.z = fmaxf(v.z, 0.f); v.w = fmaxf(v.w, 0.f);
    return v;
}

__device__ __forceinline__ float dot4(const float4 a, const float4 u) {
    return fmaf(a.x, u.x, fmaf(a.y, u.y, fmaf(a.z, u.z, a.w * u.w)));
}

__global__ void __launch_bounds__(256, 4) attn_fc_kernel(
    const float* __restrict__ hk, const float* __restrict__ hu,
    const float* __restrict__ W, const float* __restrict__ b,
    float* __restrict__ out)
{
    // [0,8192): Wt[k*128+j];  [8192,12288): staging 8 warps x 8 nodes x 64
    __shared__ float sh[12288];                          // 48 KB (4 blocks/SM)
    float* Wt = sh;
    int tid = threadIdx.x;
    for (int i = tid; i < D_FEAT * D_OUT; i += 256) {
        int k = i >> 7;            // input feat
        int j = i & 127;           // output feat
        Wt[i] = __ldg(W + j * D_FEAT + k);               // coalesced STS
    }
    __syncthreads();

    int wid = tid >> 5, lane = tid & 31;
    int half = lane >> 4, hl = lane & 15;
    unsigned hm = half ? 0xFFFF0000u : 0x0000FFFFu;
    float* stage = sh + 8192 + wid * 512;                // 8 nodes x 64 feats
    float4* stage4 = (float4*)stage;
    const float4* hk4 = (const float4*)hk;
    const float4* Wt4 = (const float4*)Wt;
    float4* out4 = (float4*)out;

    int nbase = (blockIdx.x * 8 + wid) * 8;              // 8 nodes per warp
    int hbase = nbase + half * 4;                        // 4 per half-warp

    // ---- attention: each half-warp processes its 4 nodes ----
    for (int m = 0; m < 4; m++) {
        int node = hbase + m;
        if (node >= N_NODES) break;
        float4 u = __ldg((const float4*)hu + (size_t)node * 16 + hl);
        int beg = __ldg(&g_off[node]), end = __ldg(&g_off[node + 1]);
        float4 acc = make_float4(0.f, 0.f, 0.f, 0.f);
        float denom = 0.f;

        for (int base = beg; base < end; base += 16) {
            int n = min(16, end - base);
            int srcid = (hl < n) ? __ldg(&g_esrc[base + hl]) : 0;

            float4 a0, a1;                               // pipeline prime
            {
                int s0 = __shfl_sync(hm, srcid, 0, 16);
                a0 = __ldg(hk4 + (size_t)s0 * 16 + hl);
                if (n >= 2) {
                    int s1 = __shfl_sync(hm, srcid, 1, 16);
                    a1 = __ldg(hk4 + (size_t)s1 * 16 + hl);
                }
            }
            int j = 0;
            for (; j + 2 <= n; j += 2) {
                float4 c0 = a0, c1 = a1;
                if (j + 4 <= n) {                        // prefetch next pair
                    int t0 = __shfl_sync(hm, srcid, j + 2, 16);
                    int t1 = __shfl_sync(hm, srcid, j + 3, 16);
                    a0 = __ldg(hk4 + (size_t)t0 * 16 + hl);
                    a1 = __ldg(hk4 + (size_t)t1 * 16 + hl);
                } else if (j + 3 == n) {
                    int t0 = __shfl_sync(hm, srcid, j + 2, 16);
                    a0 = __ldg(hk4 + (size_t)t0 * 16 + hl);
                }
                float p0 = dot4(c0, u);
                float p1 = dot4(c1, u);
                #pragma unroll
                for (int o = 8; o; o >>= 1) {
                    p0 += __shfl_xor_sync(hm, p0, o, 16);
                    p1 += __shfl_xor_sync(hm, p1, o, 16);
                }
                float e0 = __expf(p0);
                float e1 = __expf(p1);
                acc.x = fmaf(e0, c0.x, fmaf(e1, c1.x, acc.x));
                acc.y = fmaf(e0, c0.y, fmaf(e1, c1.y, acc.y));
                acc.z = fmaf(e0, c0.z, fmaf(e1, c1.z, acc.z));
                acc.w = fmaf(e0, c0.w, fmaf(e1, c1.w, acc.w));
                denom += e0 + e1;
            }
            if (j < n) {                                 // odd tail in a0
                float p0 = dot4(a0, u);
                #pragma unroll
                for (int o = 8; o; o >>= 1) p0 += __shfl_xor_sync(hm, p0, o, 16);
                float e0 = __expf(p0);
                acc.x = fmaf(e0, a0.x, acc.x);
                acc.y = fmaf(e0, a0.y, acc.y);
                acc.z = fmaf(e0, a0.z, acc.z);
                acc.w = fmaf(e0, a0.w, acc.w);
                denom += e0;
            }
        }
        float inv = (end > beg) ? 1.f / denom : 0.f;     // deg==0 -> zero row
        stage4[(half * 4 + m) * 16 + hl] =
            make_float4(acc.x * inv, acc.y * inv, acc.z * inv, acc.w * inv);
    }
    __syncwarp();   // both halves' staging visible before full-warp FC

    // ---- FC + relu: two 4-node groups ----
    float4 bb = __ldg((const float4*)b + lane);
    #pragma unroll
    for (int g = 0; g < 2; g++) {
        int gbase = nbase + g * 4;
        if (gbase >= N_NODES) break;
        float4 a0 = bb, a1 = bb, a2 = bb, a3 = bb;
        #pragma unroll 4
        for (int kc4 = 0; kc4 < 16; kc4++) {
            float4 w0 = Wt4[(kc4 * 4 + 0) * 32 + lane];
            float4 w1 = Wt4[(kc4 * 4 + 1) * 32 + lane];
            float4 w2 = Wt4[(kc4 * 4 + 2) * 32 + lane];
            float4 w3 = Wt4[(kc4 * 4 + 3) * 32 + lane];
            float4 r0 = stage4[(g * 4 + 0) * 16 + kc4];
            float4 r1 = stage4[(g * 4 + 1) * 16 + kc4];
            float4 r2 = stage4[(g * 4 + 2) * 16 + kc4];
            float4 r3 = stage4[(g * 4 + 3) * 16 + kc4];
            accum4(a0, r0, w0, w1, w2, w3);
            accum4(a1, r1, w0, w1, w2, w3);
            accum4(a2, r2, w0, w1, w2, w3);
            accum4(a3, r3, w0, w1, w2, w3);
        }
        if (gbase + 0 < N_NODES) out4[(size_t)(gbase + 0) * 32 + lane] = relu4(a0);
        if (gbase + 1 < N_NODES) out4[(size_t)(gbase + 1) * 32 + lane] = relu4(a1);
        if (gbase + 2 < N_NODES) out4[(size_t)(gbase + 2) * 32 + lane] = relu4(a2);
        if (gbase + 3 < N_NODES) out4[(size_t)(gbase + 3) * 32 + lane] = relu4(a3);
    }
}

// ---------------------------------------------------------------------------
// Inputs: hk[f32 N*64], hu[f32 N*64], W[f32 128*64], b[f32 128],
//         src[i32 E], dst[i32 E].  Output: f32 N*128.
// ---------------------------------------------------------------------------
extern "C" void kernel_launch(void* const* d_in, const int* in_sizes, int n_in,
                              void* d_out, int out_size) {
    const float* hk  = (const float*)d_in[0];
    const float* hu  = (const float*)d_in[1];
    const float* W   = (const float*)d_in[2];
    const float* b   = (const float*)d_in[3];
    const int*   src = (const int*)d_in[4];
    const int*   dst = (const int*)d_in[5];
    float* out = (float*)d_out;

    prep_kernel<<<PREP_BLOCKS, PREP_THREADS>>>(src, dst);
    attn_fc_kernel<<<(N_NODES + 63) / 64, 256>>>(hk, hu, W, b, out);
}